// round 1
// baseline (speedup 1.0000x reference)
#include <cuda_runtime.h>

#define BB 8
#define TT 2048
#define DD 128
#define BM 64
#define BN 64
#define SROW 132   // padded row stride in floats (33 float4 -> odd, conflict-free)

// Scratch for projections (8 MB each) — __device__ globals per harness rules.
__device__ float g_q[BB*TT*DD];
__device__ float g_k[BB*TT*DD];
__device__ float g_v[BB*TT*DD];

__device__ __forceinline__ float ex2(float x) {
    float y;
    asm("ex2.approx.ftz.f32 %0, %1;" : "=f"(y) : "f"(x));
    return y;
}

// ---------------------------------------------------------------------------
// Projection: q = x@Wq, k = x@Wk, v = x@Wv.  One block = 64 rows of x.
// ---------------------------------------------------------------------------
__global__ __launch_bounds__(256) void proj_kernel(
    const float* __restrict__ x,
    const float* __restrict__ Wq,
    const float* __restrict__ Wk,
    const float* __restrict__ Wv)
{
    __shared__ float Xs[BM * SROW];
    const int tid = threadIdx.x;
    const int row0 = blockIdx.x * BM;

    // Load 64x128 x-tile, coalesced float4
    {
        const float4* src = (const float4*)(x + (size_t)row0 * DD);
        #pragma unroll
        for (int c = 0; c < 8; c++) {
            int idx = c * 256 + tid;          // 0..2047 float4s
            int r = idx >> 5, c4 = idx & 31;
            *(float4*)&Xs[r * SROW + c4 * 4] = src[r * 32 + c4];
        }
    }
    __syncthreads();

    const int ty = tid >> 4;   // 0..15  (rows ty + 16*i)
    const int tx = tid & 15;   // 0..15  (cols tx*8 .. tx*8+7)

    const float* Ws[3]  = {Wq, Wk, Wv};
    float*       Gs[3]  = {g_q, g_k, g_v};

    for (int o = 0; o < 3; o++) {
        const float* W = Ws[o];
        float acc[4][8];
        #pragma unroll
        for (int i = 0; i < 4; i++)
            #pragma unroll
            for (int c = 0; c < 8; c++) acc[i][c] = 0.f;

        #pragma unroll 4
        for (int e = 0; e < DD; e++) {
            float4 w0 = *(const float4*)(W + e * DD + tx * 8);
            float4 w1 = *(const float4*)(W + e * DD + tx * 8 + 4);
            float xv[4];
            #pragma unroll
            for (int i = 0; i < 4; i++) xv[i] = Xs[(ty + 16 * i) * SROW + e];
            #pragma unroll
            for (int i = 0; i < 4; i++) {
                acc[i][0] += xv[i] * w0.x; acc[i][1] += xv[i] * w0.y;
                acc[i][2] += xv[i] * w0.z; acc[i][3] += xv[i] * w0.w;
                acc[i][4] += xv[i] * w1.x; acc[i][5] += xv[i] * w1.y;
                acc[i][6] += xv[i] * w1.z; acc[i][7] += xv[i] * w1.w;
            }
        }

        float* g = Gs[o] + (size_t)row0 * DD;
        #pragma unroll
        for (int i = 0; i < 4; i++) {
            int r = ty + 16 * i;
            float4 s0 = {acc[i][0], acc[i][1], acc[i][2], acc[i][3]};
            float4 s1 = {acc[i][4], acc[i][5], acc[i][6], acc[i][7]};
            *(float4*)(g + r * DD + tx * 8)     = s0;
            *(float4*)(g + r * DD + tx * 8 + 4) = s1;
        }
    }
}

// ---------------------------------------------------------------------------
// Flash attention (causal; flash-Q = k-proj, flash-K = q-proj, V = v-proj).
// BM=BN=64, 256 threads. P tile overlays the (dead) K smem buffer.
// Thread owns S rows {ty+16i}, S cols {tx+16j}; O cols {tx*4..+3} U {64+tx*4..+3}.
// ---------------------------------------------------------------------------
__global__ __launch_bounds__(256, 2) void flash_kernel(float* __restrict__ out)
{
    extern __shared__ float sm[];
    float* Qs = sm;                 // [BM][SROW]
    float* Ks = sm + BM * SROW;     // [BN][SROW]  (reused as P after S)
    float* Vs = sm + 2 * BM * SROW; // [BN][SROW]

    const int tid = threadIdx.x;
    const int it = blockIdx.x;
    const int b  = blockIdx.y;
    const int row0 = it * BM;

    const float* gq = g_q + (size_t)b * TT * DD;
    const float* gk = g_k + (size_t)b * TT * DD;
    const float* gv = g_v + (size_t)b * TT * DD;

    // Load flash-Q tile (= k projection rows row0..row0+63)
    {
        const float4* src = (const float4*)(gk + (size_t)row0 * DD);
        #pragma unroll
        for (int c = 0; c < 8; c++) {
            int idx = c * 256 + tid;
            int r = idx >> 5, c4 = idx & 31;
            *(float4*)&Qs[r * SROW + c4 * 4] = src[r * 32 + c4];
        }
    }

    const int ty = tid >> 4;
    const int tx = tid & 15;

    float m_i[4], l_i[4], acc[4][8];
    #pragma unroll
    for (int i = 0; i < 4; i++) {
        m_i[i] = -1e30f; l_i[i] = 0.f;
        #pragma unroll
        for (int c = 0; c < 8; c++) acc[i][c] = 0.f;
    }
    // (1/sqrt(128)) * log2(e)
    const float cs = 0.08838834764831845f * 1.4426950408889634f;

    for (int jt = 0; jt <= it; jt++) {
        __syncthreads();  // protect Qs (iter 0) / P+V of previous iter
        {
            const float4* ksrc = (const float4*)(gq + (size_t)jt * BN * DD);
            const float4* vsrc = (const float4*)(gv + (size_t)jt * BN * DD);
            #pragma unroll
            for (int c = 0; c < 8; c++) {
                int idx = c * 256 + tid;
                int r = idx >> 5, c4 = idx & 31;
                *(float4*)&Ks[r * SROW + c4 * 4] = ksrc[r * 32 + c4];
                *(float4*)&Vs[r * SROW + c4 * 4] = vsrc[r * 32 + c4];
            }
        }
        __syncthreads();

        // ---- S = Q . K^T (4x4 register microtile) ----
        float s[4][4];
        #pragma unroll
        for (int i = 0; i < 4; i++)
            #pragma unroll
            for (int j = 0; j < 4; j++) s[i][j] = 0.f;

        #pragma unroll 2
        for (int d = 0; d < DD; d += 4) {
            float4 qf[4], kf[4];
            #pragma unroll
            for (int i = 0; i < 4; i++) qf[i] = *(float4*)&Qs[(ty + 16 * i) * SROW + d];
            #pragma unroll
            for (int j = 0; j < 4; j++) kf[j] = *(float4*)&Ks[(tx + 16 * j) * SROW + d];
            #pragma unroll
            for (int i = 0; i < 4; i++)
                #pragma unroll
                for (int j = 0; j < 4; j++)
                    s[i][j] += qf[i].x * kf[j].x + qf[i].y * kf[j].y
                             + qf[i].z * kf[j].z + qf[i].w * kf[j].w;
        }

        // ---- causal mask on diagonal tile ----
        if (jt == it) {
            #pragma unroll
            for (int i = 0; i < 4; i++)
                #pragma unroll
                for (int j = 0; j < 4; j++)
                    if (tx + 16 * j > ty + 16 * i) s[i][j] = -1e30f;
        }

        __syncthreads();  // all S reads of Ks done before P overwrites it

        // ---- online softmax (stats in registers; 16-lane shfl groups own rows) ----
        #pragma unroll
        for (int i = 0; i < 4; i++) {
            float rmax = fmaxf(fmaxf(s[i][0], s[i][1]), fmaxf(s[i][2], s[i][3]));
            #pragma unroll
            for (int o = 8; o; o >>= 1)
                rmax = fmaxf(rmax, __shfl_xor_sync(0xffffffffu, rmax, o, 16));
            float mnew  = fmaxf(m_i[i], rmax);
            float alpha = ex2((m_i[i] - mnew) * cs);
            m_i[i] = mnew;
            float p[4], rsum = 0.f;
            #pragma unroll
            for (int j = 0; j < 4; j++) {
                p[j] = ex2((s[i][j] - mnew) * cs);
                rsum += p[j];
            }
            #pragma unroll
            for (int o = 8; o; o >>= 1)
                rsum += __shfl_xor_sync(0xffffffffu, rsum, o, 16);
            l_i[i] = l_i[i] * alpha + rsum;
            #pragma unroll
            for (int c = 0; c < 8; c++) acc[i][c] *= alpha;
            #pragma unroll
            for (int j = 0; j < 4; j++)
                Ks[(ty + 16 * i) * SROW + tx + 16 * j] = p[j];  // P tile
        }
        __syncthreads();

        // ---- O += P . V ----
        #pragma unroll 4
        for (int jj = 0; jj < BN; jj++) {
            float pv[4];
            #pragma unroll
            for (int i = 0; i < 4; i++) pv[i] = Ks[(ty + 16 * i) * SROW + jj];
            float4 v0 = *(float4*)&Vs[jj * SROW + tx * 4];
            float4 v1 = *(float4*)&Vs[jj * SROW + 64 + tx * 4];
            #pragma unroll
            for (int i = 0; i < 4; i++) {
                acc[i][0] += pv[i] * v0.x; acc[i][1] += pv[i] * v0.y;
                acc[i][2] += pv[i] * v0.z; acc[i][3] += pv[i] * v0.w;
                acc[i][4] += pv[i] * v1.x; acc[i][5] += pv[i] * v1.y;
                acc[i][6] += pv[i] * v1.z; acc[i][7] += pv[i] * v1.w;
            }
        }
    }

    // ---- normalize + write ----
    float* og = out + ((size_t)b * TT + row0) * DD;
    #pragma unroll
    for (int i = 0; i < 4; i++) {
        float inv = 1.f / l_i[i];
        int r = ty + 16 * i;
        float4 o0 = {acc[i][0] * inv, acc[i][1] * inv, acc[i][2] * inv, acc[i][3] * inv};
        float4 o1 = {acc[i][4] * inv, acc[i][5] * inv, acc[i][6] * inv, acc[i][7] * inv};
        *(float4*)(og + r * DD + tx * 4)      = o0;
        *(float4*)(og + r * DD + 64 + tx * 4) = o1;
    }
}

extern "C" void kernel_launch(void* const* d_in, const int* in_sizes, int n_in,
                              void* d_out, int out_size)
{
    const float* x  = (const float*)d_in[0];
    const float* Wq = (const float*)d_in[1];
    const float* Wk = (const float*)d_in[2];
    const float* Wv = (const float*)d_in[3];
    float* out = (float*)d_out;

    proj_kernel<<<BB * TT / BM, 256>>>(x, Wq, Wk, Wv);

    const int smem_bytes = 3 * BM * SROW * (int)sizeof(float);  // 101376
    cudaFuncSetAttribute(flash_kernel,
                         cudaFuncAttributeMaxDynamicSharedMemorySize, smem_bytes);
    dim3 grid(TT / BM, BB);
    flash_kernel<<<grid, 256, smem_bytes>>>(out);
}

// round 13
// speedup vs baseline: 4.1822x; 4.1822x over previous
#include <cuda_runtime.h>
#include <cstdint>

#define TT 2048
#define DD 128
#define BB 8

__device__ float g_q[BB*TT*DD];
__device__ float g_k[BB*TT*DD];
__device__ float g_v[BB*TT*DD];

__device__ __forceinline__ uint32_t f2tf32(float f) {
    uint32_t u; asm("cvt.rna.tf32.f32 %0, %1;" : "=r"(u) : "f"(f)); return u;
}
__device__ __forceinline__ float rtf(float f) { return __uint_as_float(f2tf32(f)); }
__device__ __forceinline__ float ex2f(float x) {
    float y; asm("ex2.approx.ftz.f32 %0, %1;" : "=f"(y) : "f"(x)); return y;
}
__device__ __forceinline__ uint32_t ldb(const float* p) { return __float_as_uint(*p); }

__device__ __forceinline__ void mma8(float c[4], const uint32_t a[4],
                                     uint32_t b0, uint32_t b1) {
    asm volatile("mma.sync.aligned.m16n8k8.row.col.f32.tf32.tf32.f32 "
                 "{%0,%1,%2,%3}, {%4,%5,%6,%7}, {%8,%9}, {%0,%1,%2,%3};"
                 : "+f"(c[0]), "+f"(c[1]), "+f"(c[2]), "+f"(c[3])
                 : "r"(a[0]), "r"(a[1]), "r"(a[2]), "r"(a[3]), "r"(b0), "r"(b1));
}

// scale * log2(e)
#define CS (0.08838834764831845f * 1.4426950408889634f)

// ---------------------------------------------------------------------------
// Projections via mma.sync tf32: q|k|v = x @ W.  128 rows/CTA, 8 warps (m16).
// Xs: [128][132] (banks 4g+t, conflict-free A loads)
// Ws: [128(e)][136(h)] (banks 8t+g, conflict-free B loads; B[k=e][n=h]=W[e][h])
// ---------------------------------------------------------------------------
#define PXS 0
#define PWS 16896                 // 128*132
#define P_SMEM ((16896 + 17408) * 4)

__global__ __launch_bounds__(256, 1) void proj_mma(
    const float* __restrict__ x, const float* __restrict__ Wq,
    const float* __restrict__ Wk, const float* __restrict__ Wv)
{
    extern __shared__ float sm[];
    float* Xs = sm + PXS;
    float* Ws = sm + PWS;
    const int tid = threadIdx.x, wid = tid >> 5, lane = tid & 31;
    const int g = lane >> 2, t = lane & 3;
    const int row0 = blockIdx.x * 128;

    // stage x tile (tf32-rounded)
    {
        const float4* src = (const float4*)(x + (size_t)row0 * DD);
        #pragma unroll
        for (int i = 0; i < 16; i++) {
            int idx = tid + 256 * i;
            int r = idx >> 5, c4 = idx & 31;
            float4 v = src[idx];
            float4 u = { rtf(v.x), rtf(v.y), rtf(v.z), rtf(v.w) };
            *(float4*)&Xs[r * 132 + c4 * 4] = u;
        }
    }
    __syncthreads();

    // A fragments for this warp's 16 rows (kept for all 3 GEMMs)
    uint32_t xf[16][4];
    {
        const float* xb = Xs + (wid * 16) * 132;
        #pragma unroll
        for (int ks = 0; ks < 16; ks++) {
            xf[ks][0] = ldb(&xb[g * 132 + 8 * ks + t]);
            xf[ks][1] = ldb(&xb[(g + 8) * 132 + 8 * ks + t]);
            xf[ks][2] = ldb(&xb[g * 132 + 8 * ks + t + 4]);
            xf[ks][3] = ldb(&xb[(g + 8) * 132 + 8 * ks + t + 4]);
        }
    }

    const float* Wp[3] = {Wq, Wk, Wv};
    float* Gp[3] = {g_q, g_k, g_v};

    for (int o = 0; o < 3; o++) {
        __syncthreads();   // previous GEMM's Ws reads done
        {
            // W is 128x128 floats = 4096 float4: 16 iterations of 256 threads.
            const float4* src = (const float4*)Wp[o];
            #pragma unroll
            for (int i = 0; i < 16; i++) {
                int idx = tid + 256 * i;
                int r = idx >> 5, c4 = idx & 31;
                float4 v = src[idx];
                float4 u = { rtf(v.x), rtf(v.y), rtf(v.z), rtf(v.w) };
                *(float4*)&Ws[r * 136 + c4 * 4] = u;
            }
        }
        __syncthreads();

        float* grow = Gp[o] + (size_t)(row0 + wid * 16) * DD;
        #pragma unroll
        for (int nt = 0; nt < 16; nt++) {
            float c[4] = {0.f, 0.f, 0.f, 0.f};
            #pragma unroll
            for (int ks = 0; ks < 16; ks++) {
                uint32_t b0 = ldb(&Ws[(8 * ks + t) * 136 + 8 * nt + g]);
                uint32_t b1 = ldb(&Ws[(8 * ks + t + 4) * 136 + 8 * nt + g]);
                mma8(c, xf[ks], b0, b1);
            }
            float2 v0 = {c[0], c[1]}, v1 = {c[2], c[3]};
            *(float2*)&grow[g * DD + 8 * nt + 2 * t]       = v0;
            *(float2*)&grow[(g + 8) * DD + 8 * nt + 2 * t] = v1;
        }
    }
}

// ---------------------------------------------------------------------------
// Flash attention via mma.sync tf32 (causal; flash-Q = k-proj, flash-K = q-proj).
// CTA = 64 query rows, 4 warps (m16/warp), 2 CTAs/SM. Key tiles of 64.
// Ks: [64][132], Vs: [64][136], Ps: [64][68] — all frag loads conflict-free.
// Grid launched big-work-first: rt = 31 - bid/8.
// ---------------------------------------------------------------------------
#define FK 0
#define FV 8448                    // 64*132
#define FP 17152                   // + 64*136
#define F_SMEM ((17152 + 64 * 68) * 4)   // 86016 B

__global__ __launch_bounds__(128, 2) void flash_mma(float* __restrict__ out)
{
    extern __shared__ float sm[];
    float* Ks = sm + FK;
    float* Vs = sm + FV;
    float* Ps = sm + FP;

    const int tid = threadIdx.x, wid = tid >> 5, lane = tid & 31;
    const int g = lane >> 2, t = lane & 3;
    const int bid = blockIdx.x;
    const int rt = 31 - (bid >> 3);     // row-tile (descending work order)
    const int b  = bid & 7;
    const int row0 = rt * 64;

    const float* gq = g_q + (size_t)b * TT * DD;
    const float* gk = g_k + (size_t)b * TT * DD;
    const float* gv = g_v + (size_t)b * TT * DD;

    // A fragments: flash-Q rows (from k-projection), tf32-rounded
    uint32_t qf[16][4];
    {
        const float* qb = gk + (size_t)(row0 + wid * 16) * DD;
        #pragma unroll
        for (int ks = 0; ks < 16; ks++) {
            qf[ks][0] = f2tf32(qb[g * DD + 8 * ks + t]);
            qf[ks][1] = f2tf32(qb[(g + 8) * DD + 8 * ks + t]);
            qf[ks][2] = f2tf32(qb[g * DD + 8 * ks + t + 4]);
            qf[ks][3] = f2tf32(qb[(g + 8) * DD + 8 * ks + t + 4]);
        }
    }

    float of[16][4];
    #pragma unroll
    for (int i = 0; i < 16; i++)
        #pragma unroll
        for (int j = 0; j < 4; j++) of[i][j] = 0.f;
    float mA = -1e30f, mB = -1e30f, lA = 0.f, lB = 0.f;

    const int rAl = wid * 16 + g;      // local row (this warp's A-row)
    const int rBl = rAl + 8;

    for (int jt = 0; jt <= rt; jt++) {
        __syncthreads();               // previous iter's Ks/Vs reads complete
        {   // stage K (from q-proj) and V tiles, tf32-rounded
            const float4* ksrc = (const float4*)(gq + (size_t)jt * 64 * DD);
            const float4* vsrc = (const float4*)(gv + (size_t)jt * 64 * DD);
            #pragma unroll
            for (int i = 0; i < 16; i++) {
                int idx = tid + 128 * i;
                int r = idx >> 5, c4 = idx & 31;
                float4 kv = ksrc[idx];
                float4 ku = { rtf(kv.x), rtf(kv.y), rtf(kv.z), rtf(kv.w) };
                *(float4*)&Ks[r * 132 + c4 * 4] = ku;
                float4 vv = vsrc[idx];
                float4 vu = { rtf(vv.x), rtf(vv.y), rtf(vv.z), rtf(vv.w) };
                *(float4*)&Vs[r * 136 + c4 * 4] = vu;
            }
        }
        __syncthreads();

        // ---- S = Q . K^T ----
        float sf[8][4];
        #pragma unroll
        for (int nt = 0; nt < 8; nt++) {
            float c[4] = {0.f, 0.f, 0.f, 0.f};
            #pragma unroll
            for (int ks = 0; ks < 16; ks++) {
                uint32_t b0 = ldb(&Ks[(8 * nt + g) * 132 + 8 * ks + t]);
                uint32_t b1 = ldb(&Ks[(8 * nt + g) * 132 + 8 * ks + t + 4]);
                mma8(c, qf[ks], b0, b1);
            }
            sf[nt][0] = c[0]; sf[nt][1] = c[1]; sf[nt][2] = c[2]; sf[nt][3] = c[3];
        }

        // ---- causal mask on diagonal key tile ----
        if (jt == rt) {
            #pragma unroll
            for (int nt = 0; nt < 8; nt++) {
                int c0 = 8 * nt + 2 * t, c1 = c0 + 1;
                if (c0 > rAl) sf[nt][0] = -1e30f;
                if (c1 > rAl) sf[nt][1] = -1e30f;
                if (c0 > rBl) sf[nt][2] = -1e30f;
                if (c1 > rBl) sf[nt][3] = -1e30f;
            }
        }

        // ---- online softmax ----
        float mxA = -1e30f, mxB = -1e30f;
        #pragma unroll
        for (int nt = 0; nt < 8; nt++) {
            mxA = fmaxf(mxA, fmaxf(sf[nt][0], sf[nt][1]));
            mxB = fmaxf(mxB, fmaxf(sf[nt][2], sf[nt][3]));
        }
        mxA = fmaxf(mxA, __shfl_xor_sync(0xffffffffu, mxA, 1));
        mxA = fmaxf(mxA, __shfl_xor_sync(0xffffffffu, mxA, 2));
        mxB = fmaxf(mxB, __shfl_xor_sync(0xffffffffu, mxB, 1));
        mxB = fmaxf(mxB, __shfl_xor_sync(0xffffffffu, mxB, 2));
        float nmA = fmaxf(mA, mxA), nmB = fmaxf(mB, mxB);
        float aA = ex2f((mA - nmA) * CS), aB = ex2f((mB - nmB) * CS);
        mA = nmA; mB = nmB;

        float sA = 0.f, sB = 0.f;
        #pragma unroll
        for (int nt = 0; nt < 8; nt++) {
            float p0 = ex2f((sf[nt][0] - nmA) * CS);
            float p1 = ex2f((sf[nt][1] - nmA) * CS);
            float p2 = ex2f((sf[nt][2] - nmB) * CS);
            float p3 = ex2f((sf[nt][3] - nmB) * CS);
            sA += p0 + p1; sB += p2 + p3;
            float2 vA = { __uint_as_float(f2tf32(p0)), __uint_as_float(f2tf32(p1)) };
            float2 vB = { __uint_as_float(f2tf32(p2)), __uint_as_float(f2tf32(p3)) };
            *(float2*)&Ps[rAl * 68 + 8 * nt + 2 * t] = vA;
            *(float2*)&Ps[rBl * 68 + 8 * nt + 2 * t] = vB;
        }
        sA += __shfl_xor_sync(0xffffffffu, sA, 1);
        sA += __shfl_xor_sync(0xffffffffu, sA, 2);
        sB += __shfl_xor_sync(0xffffffffu, sB, 1);
        sB += __shfl_xor_sync(0xffffffffu, sB, 2);
        lA = lA * aA + sA;
        lB = lB * aB + sB;
        #pragma unroll
        for (int nt = 0; nt < 16; nt++) {
            of[nt][0] *= aA; of[nt][1] *= aA;
            of[nt][2] *= aB; of[nt][3] *= aB;
        }
        __syncwarp();   // P visible warp-wide (A-frags only read own warp's rows)

        // ---- O += P . V ----
        uint32_t pf[8][4];
        #pragma unroll
        for (int ks = 0; ks < 8; ks++) {
            pf[ks][0] = ldb(&Ps[rAl * 68 + 8 * ks + t]);
            pf[ks][1] = ldb(&Ps[rBl * 68 + 8 * ks + t]);
            pf[ks][2] = ldb(&Ps[rAl * 68 + 8 * ks + t + 4]);
            pf[ks][3] = ldb(&Ps[rBl * 68 + 8 * ks + t + 4]);
        }
        #pragma unroll
        for (int nt = 0; nt < 16; nt++) {
            #pragma unroll
            for (int ks = 0; ks < 8; ks++) {
                uint32_t b0 = ldb(&Vs[(8 * ks + t) * 136 + 8 * nt + g]);
                uint32_t b1 = ldb(&Vs[(8 * ks + t + 4) * 136 + 8 * nt + g]);
                mma8(of[nt], pf[ks], b0, b1);
            }
        }
    }

    // ---- normalize + write ----
    float iA = 1.f / lA, iB = 1.f / lB;
    float* orow = out + ((size_t)b * TT + row0 + wid * 16) * DD;
    #pragma unroll
    for (int nt = 0; nt < 16; nt++) {
        float2 v0 = { of[nt][0] * iA, of[nt][1] * iA };
        float2 v1 = { of[nt][2] * iB, of[nt][3] * iB };
        *(float2*)&orow[g * DD + 8 * nt + 2 * t]       = v0;
        *(float2*)&orow[(g + 8) * DD + 8 * nt + 2 * t] = v1;
    }
}

extern "C" void kernel_launch(void* const* d_in, const int* in_sizes, int n_in,
                              void* d_out, int out_size)
{
    const float* x  = (const float*)d_in[0];
    const float* Wq = (const float*)d_in[1];
    const float* Wk = (const float*)d_in[2];
    const float* Wv = (const float*)d_in[3];
    float* out = (float*)d_out;

    cudaFuncSetAttribute(proj_mma, cudaFuncAttributeMaxDynamicSharedMemorySize, P_SMEM);
    cudaFuncSetAttribute(flash_mma, cudaFuncAttributeMaxDynamicSharedMemorySize, F_SMEM);

    proj_mma<<<BB * TT / 128, 256, P_SMEM>>>(x, Wq, Wk, Wv);
    flash_mma<<<256, 128, F_SMEM>>>(out);
}